// round 1
// baseline (speedup 1.0000x reference)
#include <cuda_runtime.h>

#define BATCH   64
#define CIN     3
#define LEN     100
#define FILTERS 64
#define L1      98
#define L2S     96
#define L3      94
#define KFC1    (FILTERS * L3)   // 6016
#define HID     10000
#define EPSB    1e-5f

// ---------------- scratch (device globals; no allocation allowed) ----------
__device__ __align__(16) float g_h1[BATCH * FILTERS * L1];
__device__ __align__(16) float g_h2[BATCH * FILTERS * L2S];
__device__ __align__(16) float g_h3[BATCH * FILTERS * L3];   // bn applied in place before fc1
__device__ __align__(16) float g_h4[BATCH * HID];
__device__ __align__(16) float g_h4n[BATCH * HID];
__device__ __align__(16) float g_h5[BATCH * HID];
__device__ __align__(16) float g_h5n[BATCH * HID];
__device__ float g_sc[HID];   // scale (reused per stage, stages are sequential)
__device__ float g_sh[HID];   // shift
__device__ float g_z[BATCH * 32]; // 30 fc3 outputs per sample

// fc3 rows actually needed: CH={0,2,8,10,3,11} x P5={0,1,33,66,99}
__constant__ int c_rows[30] = {
      0,    1,   33,   66,   99,
    200,  201,  233,  266,  299,
    800,  801,  833,  866,  899,
   1000, 1001, 1033, 1066, 1099,
    300,  301,  333,  366,  399,
   1100, 1101, 1133, 1166, 1199
};
// per-channel code: >=0 -> index into CH order, -1 -> zero, -2 -> one
__constant__ int c_inv[12] = {0, -1, 1, 4, -1, -2, -1, -1, 2, -1, 3, 5};

__device__ __forceinline__ const float* hbuf(int id) {
    switch (id) {
        case 1: return g_h1;
        case 2: return g_h2;
        case 3: return g_h3;
        case 4: return g_h4;
        default: return g_h5;
    }
}
__device__ __forceinline__ float* hbufw(int id) {
    switch (id) {
        case 1: return g_h1;
        case 2: return g_h2;
        case 3: return g_h3;
        case 4: return g_h4;
        default: return g_h5;
    }
}

// ---------------- conv1: 3->64, k=3, +bias, relu ---------------------------
__global__ void conv1_k(const float* __restrict__ x,
                        const float* __restrict__ w,
                        const float* __restrict__ b) {
    __shared__ float sx[CIN * LEN];
    __shared__ float sw[FILTERS * 9];
    __shared__ float sb[FILTERS];
    int bi = blockIdx.x;
    for (int i = threadIdx.x; i < CIN * LEN; i += blockDim.x) sx[i] = x[bi * CIN * LEN + i];
    for (int i = threadIdx.x; i < FILTERS * 9; i += blockDim.x) sw[i] = w[i];
    for (int i = threadIdx.x; i < FILTERS; i += blockDim.x) sb[i] = b[i];
    __syncthreads();
    for (int o = threadIdx.x; o < FILTERS * L1; o += blockDim.x) {
        int co = o / L1, p = o % L1;
        float acc = sb[co];
        #pragma unroll
        for (int ci = 0; ci < 3; ci++)
            #pragma unroll
            for (int t = 0; t < 3; t++)
                acc += sx[ci * LEN + p + t] * sw[co * 9 + ci * 3 + t];
        g_h1[(bi * FILTERS + co) * L1 + p] = fmaxf(acc, 0.f);
    }
}

// ---------------- per-channel BN stats over (batch, length) ----------------
__global__ void stats_c_k(int id, int P, const float* __restrict__ g,
                          const float* __restrict__ beta) {
    const float* h = hbuf(id);
    int c = blockIdx.x;
    int n = BATCH * P;
    float s = 0.f, ss = 0.f;
    for (int i = threadIdx.x; i < n; i += blockDim.x) {
        int b = i / P, p = i - b * P;
        float v = h[(b * FILTERS + c) * P + p];
        s += v; ss += v * v;
    }
    __shared__ float r1[256], r2[256];
    int tid = threadIdx.x;
    r1[tid] = s; r2[tid] = ss;
    __syncthreads();
    for (int st = 128; st > 0; st >>= 1) {
        if (tid < st) { r1[tid] += r1[tid + st]; r2[tid] += r2[tid + st]; }
        __syncthreads();
    }
    if (tid == 0) {
        float inv = 1.f / (float)n;
        float mean = r1[0] * inv;
        float var  = r2[0] * inv - mean * mean;
        float sc = g[c] * rsqrtf(var + EPSB);
        g_sc[c] = sc;
        g_sh[c] = beta[c] - mean * sc;
    }
}

// ---------------- conv2 / conv3 (64->64, k=3) with BN-on-load, +bias, relu -
__global__ __launch_bounds__(256) void conv_k(int inId, int outId, int Lin,
                        const float* __restrict__ w,
                        const float* __restrict__ bias) {
    const float* in = hbuf(inId);
    float* out = hbufw(outId);
    int Lout = Lin - 2;
    int b = blockIdx.x, cog = blockIdx.y;      // 8 output-channel groups of 8
    __shared__ float sin_[FILTERS * L1];       // max 64*98
    __shared__ float sw[8 * FILTERS * 3];
    for (int i = threadIdx.x; i < FILTERS * Lin; i += 256) {
        int ci = i / Lin;
        sin_[i] = in[(b * FILTERS + ci) * Lin + (i - ci * Lin)] * g_sc[ci] + g_sh[ci];
    }
    for (int i = threadIdx.x; i < 8 * FILTERS * 3; i += 256)
        sw[i] = w[cog * 8 * FILTERS * 3 + i];
    __syncthreads();
    for (int o = threadIdx.x; o < 8 * Lout; o += 256) {
        int col = o / Lout, p = o - col * Lout;
        int co = cog * 8 + col;
        float acc = bias[co];
        const float* wr = &sw[col * FILTERS * 3];
        #pragma unroll 8
        for (int ci = 0; ci < FILTERS; ci++) {
            const float* r = &sin_[ci * Lin + p];
            acc += r[0] * wr[ci * 3] + r[1] * wr[ci * 3 + 1] + r[2] * wr[ci * 3 + 2];
        }
        out[(b * FILTERS + co) * Lout + p] = fmaxf(acc, 0.f);
    }
}

// ---------------- apply channel BN to g_h3 in place ------------------------
__global__ void bn_apply_c_k() {
    int i = blockIdx.x * blockDim.x + threadIdx.x;
    if (i >= BATCH * FILTERS * L3) return;
    int c = (i / L3) % FILTERS;
    g_h3[i] = g_h3[i] * g_sc[c] + g_sh[c];
}

// ---------------- GEMM: C[64,N] = relu(A[64,K] @ W[N,K]^T + bias) ----------
// BM=64 (full batch), BN=64, BK=16, 256 threads, 4x4 microtile.
template <int STAGE>
__global__ __launch_bounds__(256) void gemm_k(const float* __restrict__ W,
                                              const float* __restrict__ bias,
                                              const int N, const int K) {
    const float* __restrict__ A = (STAGE == 0) ? g_h3 : g_h4n;
    float* __restrict__ C       = (STAGE == 0) ? g_h4 : g_h5;
    __shared__ float As[16][64];
    __shared__ float Bs[16][64];
    const int tid = threadIdx.x;
    const int nBase = blockIdx.x * 64;
    const int lr = tid >> 2;            // 0..63 (row within tile)
    const int lk = (tid & 3) << 2;      // 0,4,8,12
    int nl = nBase + lr; if (nl > N - 1) nl = N - 1;
    const float* Ap = A + lr * K + lk;
    const float* Bp = W + (long)nl * K + lk;
    const int tm = (tid >> 4) << 2;     // 0..60 step 4
    const int tn = (tid & 15) << 2;     // 0..60 step 4
    float acc[4][4] = {};
    float4 av = *(const float4*)Ap;
    float4 bv = *(const float4*)Bp;
    for (int k0 = 0; k0 < K; k0 += 16) {
        __syncthreads();
        As[lk + 0][lr] = av.x; As[lk + 1][lr] = av.y;
        As[lk + 2][lr] = av.z; As[lk + 3][lr] = av.w;
        Bs[lk + 0][lr] = bv.x; Bs[lk + 1][lr] = bv.y;
        Bs[lk + 2][lr] = bv.z; Bs[lk + 3][lr] = bv.w;
        __syncthreads();
        if (k0 + 16 < K) {   // prefetch next tile while computing this one
            av = *(const float4*)(Ap + k0 + 16);
            bv = *(const float4*)(Bp + k0 + 16);
        }
        #pragma unroll
        for (int kk = 0; kk < 16; kk++) {
            float4 a = *(const float4*)&As[kk][tm];
            float4 b = *(const float4*)&Bs[kk][tn];
            acc[0][0] += a.x * b.x; acc[0][1] += a.x * b.y; acc[0][2] += a.x * b.z; acc[0][3] += a.x * b.w;
            acc[1][0] += a.y * b.x; acc[1][1] += a.y * b.y; acc[1][2] += a.y * b.z; acc[1][3] += a.y * b.w;
            acc[2][0] += a.z * b.x; acc[2][1] += a.z * b.y; acc[2][2] += a.z * b.z; acc[2][3] += a.z * b.w;
            acc[3][0] += a.w * b.x; acc[3][1] += a.w * b.y; acc[3][2] += a.w * b.z; acc[3][3] += a.w * b.w;
        }
    }
    #pragma unroll
    for (int i = 0; i < 4; i++) {
        int m = tm + i;
        #pragma unroll
        for (int j = 0; j < 4; j++) {
            int nn = nBase + tn + j;
            if (nn < N) C[m * HID + nn] = fmaxf(acc[i][j] + bias[nn], 0.f);
        }
    }
}

// ---------------- per-feature BN stats over batch (64) ---------------------
__global__ void stats_f_k(int id, const float* __restrict__ g,
                          const float* __restrict__ beta) {
    int j = blockIdx.x * blockDim.x + threadIdx.x;
    if (j >= HID) return;
    const float* h = hbuf(id);
    float s = 0.f, ss = 0.f;
    #pragma unroll 4
    for (int b = 0; b < BATCH; b++) {
        float v = h[b * HID + j];
        s += v; ss += v * v;
    }
    float mean = s * (1.f / BATCH);
    float var  = ss * (1.f / BATCH) - mean * mean;
    float sc = g[j] * rsqrtf(var + EPSB);
    g_sc[j] = sc;
    g_sh[j] = beta[j] - mean * sc;
}

// sel 0: h4 -> h4n ; sel 1: h5 -> h5n
__global__ void bn_apply_f_k(int sel) {
    int i = blockIdx.x * blockDim.x + threadIdx.x;
    if (i >= BATCH * HID) return;
    int j = i % HID;
    if (sel == 0) g_h4n[i] = g_h4[i] * g_sc[j] + g_sh[j];
    else          g_h5n[i] = g_h5[i] * g_sc[j] + g_sh[j];
}

// ---------------- fc3: only the 30 observable rows -------------------------
__global__ void fc3_k(const float* __restrict__ w, const float* __restrict__ b) {
    int r = blockIdx.x;     // 0..29
    int bb = blockIdx.y;    // batch
    int row = c_rows[r];
    const float* a  = &g_h5n[bb * HID];
    const float* wr = &w[(long)row * HID];
    float s = 0.f;
    for (int i = threadIdx.x; i < HID; i += 256) s += a[i] * wr[i];
    __shared__ float rbuf[256];
    int tid = threadIdx.x;
    rbuf[tid] = s;
    __syncthreads();
    for (int st = 128; st > 0; st >>= 1) {
        if (tid < st) rbuf[tid] += rbuf[tid + st];
        __syncthreads();
    }
    if (tid == 0) g_z[bb * 30 + r] = rbuf[0] + b[row];
}

// ---------------- epilogue: build (64,12,100) output -----------------------
__global__ void epilogue_k(float* __restrict__ out) {
    int idx = blockIdx.x * blockDim.x + threadIdx.x;
    if (idx >= BATCH * 12 * LEN) return;
    int b = idx / (12 * LEN);
    int rem = idx - b * 12 * LEN;
    int ch = rem / LEN;
    int p = rem - ch * LEN;
    int code = c_inv[ch];
    float v;
    if (code == -1) v = 0.f;
    else if (code == -2) v = 1.f;
    else {
        const float* z = &g_z[b * 30 + code * 5];
        if (p == 0)       v = z[0];
        else if (p == 1)  v = z[1];
        else if (p == 33) v = z[2];
        else if (p == 66) v = z[3];
        else if (p == 99) v = z[4];
        else {
            int j = p / 33;                 // 0,1,2
            const int cl[3] = {1, 33, 66};
            float alpha = (float)(p - cl[j]) / 33.f;
            float zl = z[j + 1];
            float zr = z[j + 2];
            v = alpha * zl + (1.f - alpha) * zr;
        }
    }
    out[idx] = v;
}

// ---------------- launcher --------------------------------------------------
extern "C" void kernel_launch(void* const* d_in, const int* in_sizes, int n_in,
                              void* d_out, int out_size) {
    const float* x       = (const float*)d_in[0];
    const float* conv1_w = (const float*)d_in[1];
    const float* conv1_b = (const float*)d_in[2];
    const float* bn1_g   = (const float*)d_in[3];
    const float* bn1_b   = (const float*)d_in[4];
    const float* conv2_w = (const float*)d_in[5];
    const float* conv2_b = (const float*)d_in[6];
    const float* bn2_g   = (const float*)d_in[7];
    const float* bn2_b   = (const float*)d_in[8];
    const float* conv3_w = (const float*)d_in[9];
    const float* conv3_b = (const float*)d_in[10];
    const float* bn3_g   = (const float*)d_in[11];
    const float* bn3_b   = (const float*)d_in[12];
    const float* fc1_w   = (const float*)d_in[13];
    const float* fc1_b   = (const float*)d_in[14];
    const float* bn4_g   = (const float*)d_in[15];
    const float* bn4_b   = (const float*)d_in[16];
    const float* fc2_w   = (const float*)d_in[17];
    const float* fc2_b   = (const float*)d_in[18];
    const float* bn5_g   = (const float*)d_in[19];
    const float* bn5_b   = (const float*)d_in[20];
    const float* fc3_w   = (const float*)d_in[21];
    const float* fc3_b   = (const float*)d_in[22];
    float* out = (float*)d_out;

    conv1_k<<<BATCH, 256>>>(x, conv1_w, conv1_b);
    stats_c_k<<<FILTERS, 256>>>(1, L1, bn1_g, bn1_b);
    conv_k<<<dim3(BATCH, 8), 256>>>(1, 2, L1, conv2_w, conv2_b);
    stats_c_k<<<FILTERS, 256>>>(2, L2S, bn2_g, bn2_b);
    conv_k<<<dim3(BATCH, 8), 256>>>(2, 3, L2S, conv3_w, conv3_b);
    stats_c_k<<<FILTERS, 256>>>(3, L3, bn3_g, bn3_b);
    bn_apply_c_k<<<(BATCH * FILTERS * L3 + 255) / 256, 256>>>();

    gemm_k<0><<<(HID + 63) / 64, 256>>>(fc1_w, fc1_b, HID, KFC1);
    stats_f_k<<<(HID + 255) / 256, 256>>>(4, bn4_g, bn4_b);
    bn_apply_f_k<<<(BATCH * HID + 255) / 256, 256>>>(0);

    gemm_k<1><<<(HID + 63) / 64, 256>>>(fc2_w, fc2_b, HID, HID);
    stats_f_k<<<(HID + 255) / 256, 256>>>(5, bn5_g, bn5_b);
    bn_apply_f_k<<<(BATCH * HID + 255) / 256, 256>>>(1);

    fc3_k<<<dim3(30, BATCH), 256>>>(fc3_w, fc3_b);
    epilogue_k<<<(BATCH * 12 * LEN + 255) / 256, 256>>>(out);
}